// round 5
// baseline (speedup 1.0000x reference)
#include <cuda_runtime.h>
#include <math.h>

#define BB 8
#define CC 64
#define LL 2048
#define MM 1024
#define GG 4
#define CPG 16
#define HH 8
#define EE 8
#define EPSV 1e-5f

typedef unsigned long long ull;

// ---------------- packed f32x2 helpers ----------------
__device__ __forceinline__ ull pk2(float lo, float hi) {
    ull r;
    asm("mov.b64 %0, {%1, %2};" : "=l"(r) : "r"(__float_as_uint(lo)), "r"(__float_as_uint(hi)));
    return r;
}
__device__ __forceinline__ void upk2(ull v, float& lo, float& hi) {
    unsigned int a, b;
    asm("mov.b64 {%0, %1}, %2;" : "=r"(a), "=r"(b) : "l"(v));
    lo = __uint_as_float(a); hi = __uint_as_float(b);
}
__device__ __forceinline__ ull ffma2(ull a, ull b, ull c) {
    ull d;
    asm("fma.rn.f32x2 %0, %1, %2, %3;" : "=l"(d) : "l"(a), "l"(b), "l"(c));
    return d;
}
__device__ __forceinline__ ull fmul2(ull a, ull b) {
    ull d;
    asm("mul.rn.f32x2 %0, %1, %2;" : "=l"(d) : "l"(a), "l"(b));
    return d;
}
__device__ __forceinline__ float ex2f(float x) {
    float r;
    asm("ex2.approx.f32 %0, %1;" : "=f"(r) : "f"(x));
    return r;
}

// ---------------- scratch ----------------
__device__ float g_xat[BB*CC*LL];
__device__ float g_qp [BB*CC*LL];
__device__ float g_xa [BB*CC*MM];
__device__ float g_v  [BB*CC*MM];
__device__ float g_v1 [BB*CC*MM];
__device__ float g_out[BB*CC*LL];
__device__ float g_xs [BB*CC*LL];
__device__ float g_xs2[BB*CC*LL];
__device__ float g_pn [2*BB*CC*LL];   // partial numerators per split
__device__ float g_pd [2*BB*HH*LL];   // partial denominators per split
__device__ float g_s1d[CC];
__device__ float g_s2d[CC];
__device__ float g_s1f[CC];
__device__ float g_s2f[CC];

// ---------------- K1: q conv -> sigmoid gate -> x_atten -> q_ conv ----------------
__global__ void __launch_bounds__(256) k1_gate(const float* __restrict__ x,
                                               const float* __restrict__ qw,
                                               const float* __restrict__ kw) {
    __shared__ float qws[CPG*CPG], kws[CPG*CPG];
    int t = threadIdx.x;
    int g = blockIdx.y;
    if (blockIdx.x == 0 && g == 0 && t < CC) {
        g_s1d[t] = 0.f; g_s2d[t] = 0.f; g_s1f[t] = 0.f; g_s2f[t] = 0.f;
    }
    if (t < CPG*CPG) {
        qws[t] = qw[(size_t)g*CPG*CPG + t];
        kws[t] = kw[(size_t)g*CPG*CPG + t];
    }
    __syncthreads();
    int gl = blockIdx.x * 256 + t;
    int b = gl >> 11, l = gl & (LL-1);
    size_t base = (size_t)b*CC*LL + l + (size_t)g*CPG*LL;
    float xv[CPG], xa[CPG];
    #pragma unroll
    for (int i = 0; i < CPG; i++) xv[i] = x[base + (size_t)i*LL];
    #pragma unroll
    for (int c = 0; c < CPG; c++) {
        float s = 0.f;
        #pragma unroll
        for (int i = 0; i < CPG; i++) s = fmaf(qws[c*CPG+i], xv[i], s);
        xa[c] = xv[c] / (1.f + __expf(-s));
    }
    #pragma unroll
    for (int i = 0; i < CPG; i++) g_xat[base + (size_t)i*LL] = xa[i];
    #pragma unroll
    for (int c = 0; c < CPG; c++) {
        float s = 0.f;
        #pragma unroll
        for (int i = 0; i < CPG; i++) s = fmaf(kws[c*CPG+i], xa[i], s);
        g_qp[base + (size_t)c*LL] = s;
    }
}

// ---------------- K2: odd/even shuffle + down conv + BN stats ----------------
#define TM2 32
__global__ void __launch_bounds__(256) k2_down(const float* __restrict__ dw) {
    __shared__ float xt[CC][2*TM2 + 4];
    int t = threadIdx.x;
    int m0 = blockIdx.x * TM2, b = blockIdx.y;
    int l0 = 2*m0 - 2;
    const int W = 2*TM2 + 4;
    for (int idx = t; idx < CC*W; idx += 256) {
        int i = idx / W, s = idx % W;
        int l = l0 + s;
        xt[i][s] = (l >= 0 && l < LL) ? g_xat[((size_t)b*CC + i)*LL + l] : 0.f;
    }
    __syncthreads();
    int o = t >> 2, qq = t & 3;
    float acc[8];
    #pragma unroll
    for (int j = 0; j < 8; j++) acc[j] = 0.f;
    const float* wb = dw + (size_t)o*CC*3;
    int sb = 2*(qq*8) + ((o < 32) ? 1 : 0);
    for (int i = 0; i < CC; i++) {
        float w0 = __ldg(wb + i*3 + 0), w1 = __ldg(wb + i*3 + 1), w2 = __ldg(wb + i*3 + 2);
        const float* row = xt[i];
        float a0 = row[sb], a1 = row[sb+2];
        #pragma unroll
        for (int j = 0; j < 8; j++) {
            float a2 = row[sb + 4 + 2*j];
            acc[j] = fmaf(w0, a0, fmaf(w1, a1, fmaf(w2, a2, acc[j])));
            a0 = a1; a1 = a2;
        }
    }
    float s1 = 0.f, s2 = 0.f;
    size_t base = ((size_t)b*CC + o)*MM + m0 + qq*8;
    #pragma unroll
    for (int j = 0; j < 8; j++) { float v = acc[j]; g_xa[base + j] = v; s1 += v; s2 = fmaf(v, v, s2); }
    s1 += __shfl_xor_sync(0xffffffffu, s1, 1); s2 += __shfl_xor_sync(0xffffffffu, s2, 1);
    s1 += __shfl_xor_sync(0xffffffffu, s1, 2); s2 += __shfl_xor_sync(0xffffffffu, s2, 2);
    if (qq == 0) { atomicAdd(&g_s1d[o], s1); atomicAdd(&g_s2d[o], s2); }
}

// ---------------- K3: BN + ReLU + v/v1 pointwise grouped convs ----------------
__global__ void __launch_bounds__(256) k3_vconv(const float* __restrict__ vw,
                                                const float* __restrict__ v1w,
                                                const float* __restrict__ dgam,
                                                const float* __restrict__ dbet) {
    __shared__ float sc[CPG], sh[CPG], vws[CPG*CPG], v1ws[CPG*CPG];
    int t = threadIdx.x;
    int g = blockIdx.y;
    if (t < CPG) {
        int c = g*CPG + t;
        const float invn = 1.f / (float)(BB*MM);
        float mean = g_s1d[c] * invn;
        float var  = g_s2d[c] * invn - mean*mean;
        float s = dgam[c] * rsqrtf(var + EPSV);
        sc[t] = s; sh[t] = dbet[c] - mean*s;
    }
    if (t < CPG*CPG) {
        vws[t]  = vw [(size_t)g*CPG*CPG + t];
        v1ws[t] = v1w[(size_t)g*CPG*CPG + t];
    }
    __syncthreads();
    int gl = blockIdx.x * 256 + t;
    int b = gl >> 10, m = gl & (MM-1);
    size_t base = (size_t)b*CC*MM + m + (size_t)g*CPG*MM;
    float xr[CPG];
    #pragma unroll
    for (int i = 0; i < CPG; i++)
        xr[i] = fmaxf(0.f, fmaf(g_xa[base + (size_t)i*MM], sc[i], sh[i]));
    #pragma unroll
    for (int c = 0; c < CPG; c++) {
        float s = 0.f, s1 = 0.f;
        #pragma unroll
        for (int i = 0; i < CPG; i++) {
            s  = fmaf(vws [c*CPG+i], xr[i], s);
            s1 = fmaf(v1ws[c*CPG+i], xr[i], s1);
        }
        g_v [base + (size_t)c*MM] = s;
        g_v1[base + (size_t)c*MM] = s1;
    }
}

// ---------------- K4: attention, 2 l's/thread, 512 blocks, 3 blocks/SM ----------------
#define SPL 2
#define MSP (MM/SPL)          // 512 m's per block
#define KD_STRIDE 20
#define VS_STRIDE 12
#define KD_FLOATS (MSP*KD_STRIDE)
#define K4_SMEM ((KD_FLOATS + MSP*VS_STRIDE)*4)   // 65536 bytes

__global__ void __launch_bounds__(256, 3) k4_attn() {
    extern __shared__ float sm4[];
    float* ksm = sm4;
    float* vsm = sm4 + KD_FLOATS;
    int t = threadIdx.x;
    int bh = blockIdx.y; int b = bh >> 3, h = bh & 7;
    int sp = blockIdx.z; int mb = sp * MSP;
    size_t vbase = ((size_t)b*CC + h*EE)*MM + mb;
    const float SCL = 0.35355339059327373f * 1.4426950408889634f;
    for (int m = t; m < MSP; m += 256) {
        float kv[EE], vv[EE];
        #pragma unroll
        for (int e = 0; e < EE; e++) {
            kv[e] = g_v [vbase + (size_t)e*MM + m] * SCL;
            vv[e] = g_v1[vbase + (size_t)e*MM + m];
        }
        float* kr = ksm + m*KD_STRIDE;
        ((float4*)kr)[0] = make_float4(kv[0], kv[0], kv[1], kv[1]);
        ((float4*)kr)[1] = make_float4(kv[2], kv[2], kv[3], kv[3]);
        ((float4*)kr)[2] = make_float4(kv[4], kv[4], kv[5], kv[5]);
        ((float4*)kr)[3] = make_float4(kv[6], kv[6], kv[7], kv[7]);
        float* vr = vsm + m*VS_STRIDE;
        ((float4*)vr)[0] = make_float4(vv[0], vv[1], vv[2], vv[3]);
        ((float4*)vr)[1] = make_float4(vv[4], vv[5], vv[6], vv[7]);
    }
    __syncthreads();

    int lb = blockIdx.x * 512 + t;     // lA = lb, lB = lb + 256
    size_t qb = ((size_t)b*CC + h*EE)*LL + lb;
    ull q01[EE];
    #pragma unroll
    for (int e = 0; e < EE; e++) {
        size_t r = qb + (size_t)e*LL;
        q01[e] = pk2(g_qp[r], g_qp[r + 256]);
    }
    ull aA[4] = {0,0,0,0}, aB[4] = {0,0,0,0};
    float smA = 0.f, smB = 0.f;

    #pragma unroll 4
    for (int m = 0; m < MSP; m++) {
        const ulonglong2* kr = (const ulonglong2*)(ksm + m*KD_STRIDE);
        ulonglong2 kA = kr[0], kB = kr[1], kC = kr[2], kD = kr[3];
        ull s01 = fmul2(q01[0], kA.x);
        s01 = ffma2(q01[1], kA.y, s01);
        s01 = ffma2(q01[2], kB.x, s01);
        s01 = ffma2(q01[3], kB.y, s01);
        s01 = ffma2(q01[4], kC.x, s01);
        s01 = ffma2(q01[5], kC.y, s01);
        s01 = ffma2(q01[6], kD.x, s01);
        s01 = ffma2(q01[7], kD.y, s01);
        float s0, s1;
        upk2(s01, s0, s1);
        float p0 = ex2f(s0), p1 = ex2f(s1);
        smA += p0; smB += p1;
        ull pA = pk2(p0, p0), pB = pk2(p1, p1);
        const ulonglong2* vr = (const ulonglong2*)(vsm + m*VS_STRIDE);
        ulonglong2 vA = vr[0], vB = vr[1];
        aA[0] = ffma2(pA, vA.x, aA[0]); aA[1] = ffma2(pA, vA.y, aA[1]);
        aA[2] = ffma2(pA, vB.x, aA[2]); aA[3] = ffma2(pA, vB.y, aA[3]);
        aB[0] = ffma2(pB, vA.x, aB[0]); aB[1] = ffma2(pB, vA.y, aB[1]);
        aB[2] = ffma2(pB, vB.x, aB[2]); aB[3] = ffma2(pB, vB.y, aB[3]);
    }

    // write partial sums (no division yet)
    float* pn = g_pn + (size_t)sp*BB*CC*LL;
    float* pd = g_pd + (size_t)sp*BB*HH*LL;
    size_t di = (size_t)bh*LL + lb;
    pd[di      ] = smA;
    pd[di + 256] = smB;
    #pragma unroll
    for (int j = 0; j < 4; j++) {
        float x0, x1, y0, y1;
        upk2(aA[j], x0, x1); upk2(aB[j], y0, y1);
        size_t r0 = qb + (size_t)(2*j)*LL;
        size_t r1 = r0 + LL;
        pn[r0      ] = x0; pn[r1      ] = x1;
        pn[r0 + 256] = y0; pn[r1 + 256] = y1;
    }
}

// ---------------- K4b: combine partials -> out, xs ----------------
__global__ void __launch_bounds__(256) k4b_combine() {
    int idx = blockIdx.x * 256 + threadIdx.x;
    int l  = idx & (LL-1);
    int ce = (idx >> 11) & (CC-1);
    int b  = idx >> 17;
    size_t di = ((size_t)(b*HH + (ce >> 3)))*LL + l;
    float den = g_pd[di] + g_pd[(size_t)BB*HH*LL + di];
    float num = g_pn[idx] + g_pn[(size_t)BB*CC*LL + idx];
    float o = num * (1.f / den);
    g_out[idx] = o;
    g_xs[idx]  = o + g_xat[idx];
}

// ---------------- K5: out conv + residual + stats ----------------
#define TL5 128
__global__ void __launch_bounds__(256) k5_outconv(const float* __restrict__ ow) {
    __shared__ float xcs[48][TL5 + 2];
    int t = threadIdx.x;
    int l0 = blockIdx.x * TL5, g = blockIdx.y, b = blockIdx.z;
    const int W = TL5 + 2;
    for (int idx = t; idx < 48*W; idx += 256) {
        int j = idx / W, s = idx % W;
        int l = l0 - 1 + s;
        int u = g*48 + j;
        float val = 0.f;
        if (l >= 0 && l < LL) {
            const float* src; int ch;
            if      (u < 64)  { src = g_xs;  ch = u; }
            else if (u < 128) { src = g_qp;  ch = u - 64; }
            else              { src = g_out; ch = u - 128; }
            val = src[((size_t)b*CC + ch)*LL + l];
        }
        xcs[j][s] = val;
    }
    __syncthreads();
    int cl = t >> 4, sub = t & 15;
    int c = g*CPG + cl;
    int lbase = sub * 8;
    float acc[8];
    #pragma unroll
    for (int jj = 0; jj < 8; jj++) acc[jj] = 0.f;
    const float* wb = ow + (size_t)c*48*3;
    for (int j = 0; j < 48; j++) {
        float w0 = __ldg(wb + j*3 + 0), w1 = __ldg(wb + j*3 + 1), w2 = __ldg(wb + j*3 + 2);
        const float* row = xcs[j];
        float a0 = row[lbase], a1 = row[lbase+1];
        #pragma unroll
        for (int jj = 0; jj < 8; jj++) {
            float a2 = row[lbase + 2 + jj];
            acc[jj] = fmaf(w0, a0, fmaf(w1, a1, fmaf(w2, a2, acc[jj])));
            a0 = a1; a1 = a2;
        }
    }
    float s1 = 0.f, s2 = 0.f;
    size_t base = ((size_t)b*CC + c)*LL + l0 + lbase;
    #pragma unroll
    for (int jj = 0; jj < 8; jj++) {
        float v = acc[jj] + g_xs[base + jj];
        g_xs2[base + jj] = v;
        s1 += v; s2 = fmaf(v, v, s2);
    }
    #pragma unroll
    for (int k = 1; k < 16; k <<= 1) {
        s1 += __shfl_xor_sync(0xffffffffu, s1, k);
        s2 += __shfl_xor_sync(0xffffffffu, s2, k);
    }
    if (sub == 0) { atomicAdd(&g_s1f[c], s1); atomicAdd(&g_s2f[c], s2); }
}

// ---------------- K6: final BN + ReLU -> output ----------------
__global__ void __launch_bounds__(256) k6_final(const float* __restrict__ gam,
                                                const float* __restrict__ bet,
                                                float* __restrict__ out) {
    int idx = blockIdx.x * 256 + threadIdx.x;
    int c = (idx >> 11) & (CC-1);
    const float invn = 1.f / (float)(BB*LL);
    float mean = g_s1f[c] * invn;
    float var  = g_s2f[c] * invn - mean*mean;
    float s  = gam[c] * rsqrtf(var + EPSV);
    float shv = bet[c] - mean*s;
    out[idx] = fmaxf(0.f, fmaf(g_xs2[idx], s, shv));
}

// ---------------- launch ----------------
extern "C" void kernel_launch(void* const* d_in, const int* in_sizes, int n_in,
                              void* d_out, int out_size) {
    const float* x   = (const float*)d_in[0];
    const float* qw  = (const float*)d_in[1];
    const float* kw  = (const float*)d_in[2];
    const float* vw  = (const float*)d_in[3];
    const float* v1w = (const float*)d_in[4];
    const float* ow  = (const float*)d_in[5];
    const float* dw  = (const float*)d_in[6];
    const float* dg  = (const float*)d_in[7];
    const float* db  = (const float*)d_in[8];
    const float* gam = (const float*)d_in[9];
    const float* bet = (const float*)d_in[10];
    float* out = (float*)d_out;

    static int configured = 0;
    if (!configured) {
        cudaFuncSetAttribute(k4_attn, cudaFuncAttributeMaxDynamicSharedMemorySize, K4_SMEM);
        configured = 1;
    }

    k1_gate<<<dim3((BB*LL)/256, GG), 256>>>(x, qw, kw);
    k2_down<<<dim3(MM/TM2, BB), 256>>>(dw);
    k3_vconv<<<dim3((BB*MM)/256, GG), 256>>>(vw, v1w, dg, db);
    k4_attn<<<dim3(LL/512, BB*HH, SPL), 256, K4_SMEM>>>();
    k4b_combine<<<(BB*CC*LL)/256, 256>>>();
    k5_outconv<<<dim3(LL/TL5, GG, BB), 256>>>(ow);
    k6_final<<<(BB*CC*LL)/256, 256>>>(gam, bet, out);
}

// round 6
// speedup vs baseline: 1.0159x; 1.0159x over previous
#include <cuda_runtime.h>
#include <math.h>

#define BB 8
#define CC 64
#define LL 2048
#define MM 1024
#define GG 4
#define CPG 16
#define HH 8
#define EE 8
#define EPSV 1e-5f

typedef unsigned long long ull;

// ---------------- packed f32x2 helpers ----------------
__device__ __forceinline__ ull pk2(float lo, float hi) {
    ull r;
    asm("mov.b64 %0, {%1, %2};" : "=l"(r) : "r"(__float_as_uint(lo)), "r"(__float_as_uint(hi)));
    return r;
}
__device__ __forceinline__ void upk2(ull v, float& lo, float& hi) {
    unsigned int a, b;
    asm("mov.b64 {%0, %1}, %2;" : "=r"(a), "=r"(b) : "l"(v));
    lo = __uint_as_float(a); hi = __uint_as_float(b);
}
__device__ __forceinline__ ull ffma2(ull a, ull b, ull c) {
    ull d;
    asm("fma.rn.f32x2 %0, %1, %2, %3;" : "=l"(d) : "l"(a), "l"(b), "l"(c));
    return d;
}
__device__ __forceinline__ ull fmul2(ull a, ull b) {
    ull d;
    asm("mul.rn.f32x2 %0, %1, %2;" : "=l"(d) : "l"(a), "l"(b));
    return d;
}
__device__ __forceinline__ float ex2f(float x) {
    float r;
    asm("ex2.approx.f32 %0, %1;" : "=f"(r) : "f"(x));
    return r;
}

// ---------------- scratch ----------------
#define SPL 4
#define N1 (BB*CC*LL)
#define D1 (BB*HH*LL)
__device__ float g_xat[BB*CC*LL];
__device__ float g_qp [BB*CC*LL];
__device__ float g_xa [BB*CC*MM];
__device__ float g_v  [BB*CC*MM];
__device__ float g_v1 [BB*CC*MM];
__device__ float g_xs2[BB*CC*LL];
__device__ float g_pn [SPL*N1];   // partial numerators per split
__device__ float g_pd [SPL*D1];   // partial denominators per split
__device__ float g_s1d[CC];
__device__ float g_s2d[CC];
__device__ float g_s1f[CC];
__device__ float g_s2f[CC];

// combine partials -> attention output o for (flat idx, denom idx)
__device__ __forceinline__ float comb_o(size_t idx, size_t di) {
    float den = g_pd[di] + g_pd[D1 + di] + g_pd[2*(size_t)D1 + di] + g_pd[3*(size_t)D1 + di];
    float num = g_pn[idx] + g_pn[N1 + idx] + g_pn[2*(size_t)N1 + idx] + g_pn[3*(size_t)N1 + idx];
    return num * (1.f / den);
}

// ---------------- K1: q conv -> sigmoid gate -> x_atten -> q_ conv ----------------
__global__ void __launch_bounds__(256) k1_gate(const float* __restrict__ x,
                                               const float* __restrict__ qw,
                                               const float* __restrict__ kw) {
    __shared__ float qws[CPG*CPG], kws[CPG*CPG];
    int t = threadIdx.x;
    int g = blockIdx.y;
    if (blockIdx.x == 0 && g == 0 && t < CC) {
        g_s1d[t] = 0.f; g_s2d[t] = 0.f; g_s1f[t] = 0.f; g_s2f[t] = 0.f;
    }
    if (t < CPG*CPG) {
        qws[t] = qw[(size_t)g*CPG*CPG + t];
        kws[t] = kw[(size_t)g*CPG*CPG + t];
    }
    __syncthreads();
    int gl = blockIdx.x * 256 + t;
    int b = gl >> 11, l = gl & (LL-1);
    size_t base = (size_t)b*CC*LL + l + (size_t)g*CPG*LL;
    float xv[CPG], xa[CPG];
    #pragma unroll
    for (int i = 0; i < CPG; i++) xv[i] = x[base + (size_t)i*LL];
    #pragma unroll
    for (int c = 0; c < CPG; c++) {
        float s = 0.f;
        #pragma unroll
        for (int i = 0; i < CPG; i++) s = fmaf(qws[c*CPG+i], xv[i], s);
        xa[c] = xv[c] / (1.f + __expf(-s));
    }
    #pragma unroll
    for (int i = 0; i < CPG; i++) g_xat[base + (size_t)i*LL] = xa[i];
    #pragma unroll
    for (int c = 0; c < CPG; c++) {
        float s = 0.f;
        #pragma unroll
        for (int i = 0; i < CPG; i++) s = fmaf(kws[c*CPG+i], xa[i], s);
        g_qp[base + (size_t)c*LL] = s;
    }
}

// ---------------- K2: odd/even shuffle + down conv + BN stats ----------------
#define TM2 32
__global__ void __launch_bounds__(256) k2_down(const float* __restrict__ dw) {
    __shared__ float xt[CC][2*TM2 + 4];
    int t = threadIdx.x;
    int m0 = blockIdx.x * TM2, b = blockIdx.y;
    int l0 = 2*m0 - 2;
    const int W = 2*TM2 + 4;
    for (int idx = t; idx < CC*W; idx += 256) {
        int i = idx / W, s = idx % W;
        int l = l0 + s;
        xt[i][s] = (l >= 0 && l < LL) ? g_xat[((size_t)b*CC + i)*LL + l] : 0.f;
    }
    __syncthreads();
    int o = t >> 2, qq = t & 3;
    float acc[8];
    #pragma unroll
    for (int j = 0; j < 8; j++) acc[j] = 0.f;
    const float* wb = dw + (size_t)o*CC*3;
    int sb = 2*(qq*8) + ((o < 32) ? 1 : 0);
    for (int i = 0; i < CC; i++) {
        float w0 = __ldg(wb + i*3 + 0), w1 = __ldg(wb + i*3 + 1), w2 = __ldg(wb + i*3 + 2);
        const float* row = xt[i];
        float a0 = row[sb], a1 = row[sb+2];
        #pragma unroll
        for (int j = 0; j < 8; j++) {
            float a2 = row[sb + 4 + 2*j];
            acc[j] = fmaf(w0, a0, fmaf(w1, a1, fmaf(w2, a2, acc[j])));
            a0 = a1; a1 = a2;
        }
    }
    float s1 = 0.f, s2 = 0.f;
    size_t base = ((size_t)b*CC + o)*MM + m0 + qq*8;
    #pragma unroll
    for (int j = 0; j < 8; j++) { float v = acc[j]; g_xa[base + j] = v; s1 += v; s2 = fmaf(v, v, s2); }
    s1 += __shfl_xor_sync(0xffffffffu, s1, 1); s2 += __shfl_xor_sync(0xffffffffu, s2, 1);
    s1 += __shfl_xor_sync(0xffffffffu, s1, 2); s2 += __shfl_xor_sync(0xffffffffu, s2, 2);
    if (qq == 0) { atomicAdd(&g_s1d[o], s1); atomicAdd(&g_s2d[o], s2); }
}

// ---------------- K3: BN + ReLU + v/v1 pointwise grouped convs ----------------
__global__ void __launch_bounds__(256) k3_vconv(const float* __restrict__ vw,
                                                const float* __restrict__ v1w,
                                                const float* __restrict__ dgam,
                                                const float* __restrict__ dbet) {
    __shared__ float sc[CPG], sh[CPG], vws[CPG*CPG], v1ws[CPG*CPG];
    int t = threadIdx.x;
    int g = blockIdx.y;
    if (t < CPG) {
        int c = g*CPG + t;
        const float invn = 1.f / (float)(BB*MM);
        float mean = g_s1d[c] * invn;
        float var  = g_s2d[c] * invn - mean*mean;
        float s = dgam[c] * rsqrtf(var + EPSV);
        sc[t] = s; sh[t] = dbet[c] - mean*s;
    }
    if (t < CPG*CPG) {
        vws[t]  = vw [(size_t)g*CPG*CPG + t];
        v1ws[t] = v1w[(size_t)g*CPG*CPG + t];
    }
    __syncthreads();
    int gl = blockIdx.x * 256 + t;
    int b = gl >> 10, m = gl & (MM-1);
    size_t base = (size_t)b*CC*MM + m + (size_t)g*CPG*MM;
    float xr[CPG];
    #pragma unroll
    for (int i = 0; i < CPG; i++)
        xr[i] = fmaxf(0.f, fmaf(g_xa[base + (size_t)i*MM], sc[i], sh[i]));
    #pragma unroll
    for (int c = 0; c < CPG; c++) {
        float s = 0.f, s1 = 0.f;
        #pragma unroll
        for (int i = 0; i < CPG; i++) {
            s  = fmaf(vws [c*CPG+i], xr[i], s);
            s1 = fmaf(v1ws[c*CPG+i], xr[i], s1);
        }
        g_v [base + (size_t)c*MM] = s;
        g_v1[base + (size_t)c*MM] = s1;
    }
}

// ---------------- K4: attention, 4 l's/thread, SPL=4 m-splits, partial sums ----------------
#define MSP (MM/SPL)          // 256 m's per block
#define KD_STRIDE 20
#define VS_STRIDE 12
#define KD_FLOATS (MSP*KD_STRIDE)
#define K4_SMEM ((KD_FLOATS + MSP*VS_STRIDE)*4)   // 32768 bytes

__global__ void __launch_bounds__(256) k4_attn() {
    extern __shared__ float sm4[];
    float* ksm = sm4;
    float* vsm = sm4 + KD_FLOATS;
    int t = threadIdx.x;
    int bh = blockIdx.y; int b = bh >> 3, h = bh & 7;
    int sp = blockIdx.z; int mb = sp * MSP;
    size_t vbase = ((size_t)b*CC + h*EE)*MM + mb;
    const float SCL = 0.35355339059327373f * 1.4426950408889634f;
    for (int m = t; m < MSP; m += 256) {
        float kv[EE], vv[EE];
        #pragma unroll
        for (int e = 0; e < EE; e++) {
            kv[e] = g_v [vbase + (size_t)e*MM + m] * SCL;
            vv[e] = g_v1[vbase + (size_t)e*MM + m];
        }
        float* kr = ksm + m*KD_STRIDE;
        ((float4*)kr)[0] = make_float4(kv[0], kv[0], kv[1], kv[1]);
        ((float4*)kr)[1] = make_float4(kv[2], kv[2], kv[3], kv[3]);
        ((float4*)kr)[2] = make_float4(kv[4], kv[4], kv[5], kv[5]);
        ((float4*)kr)[3] = make_float4(kv[6], kv[6], kv[7], kv[7]);
        float* vr = vsm + m*VS_STRIDE;
        ((float4*)vr)[0] = make_float4(vv[0], vv[1], vv[2], vv[3]);
        ((float4*)vr)[1] = make_float4(vv[4], vv[5], vv[6], vv[7]);
    }
    __syncthreads();

    int lb = blockIdx.x * 1024 + t;   // lA=lb, lB=+256, lC=+512, lD=+768
    size_t qb = ((size_t)b*CC + h*EE)*LL + lb;
    ull q01[EE], q23[EE];
    #pragma unroll
    for (int e = 0; e < EE; e++) {
        size_t r = qb + (size_t)e*LL;
        q01[e] = pk2(g_qp[r],       g_qp[r + 256]);
        q23[e] = pk2(g_qp[r + 512], g_qp[r + 768]);
    }
    ull aA[4] = {0,0,0,0}, aB[4] = {0,0,0,0}, aC[4] = {0,0,0,0}, aD[4] = {0,0,0,0};
    float smA = 0.f, smB = 0.f, smC = 0.f, smD = 0.f;

    #pragma unroll 2
    for (int m = 0; m < MSP; m++) {
        const ulonglong2* kr = (const ulonglong2*)(ksm + m*KD_STRIDE);
        ulonglong2 kA = kr[0], kB = kr[1], kC = kr[2], kD = kr[3];
        ull s01 = fmul2(q01[0], kA.x);
        ull s23 = fmul2(q23[0], kA.x);
        s01 = ffma2(q01[1], kA.y, s01);  s23 = ffma2(q23[1], kA.y, s23);
        s01 = ffma2(q01[2], kB.x, s01);  s23 = ffma2(q23[2], kB.x, s23);
        s01 = ffma2(q01[3], kB.y, s01);  s23 = ffma2(q23[3], kB.y, s23);
        s01 = ffma2(q01[4], kC.x, s01);  s23 = ffma2(q23[4], kC.x, s23);
        s01 = ffma2(q01[5], kC.y, s01);  s23 = ffma2(q23[5], kC.y, s23);
        s01 = ffma2(q01[6], kD.x, s01);  s23 = ffma2(q23[6], kD.x, s23);
        s01 = ffma2(q01[7], kD.y, s01);  s23 = ffma2(q23[7], kD.y, s23);
        float s0, s1, s2, s3;
        upk2(s01, s0, s1); upk2(s23, s2, s3);
        float p0 = ex2f(s0), p1 = ex2f(s1), p2 = ex2f(s2), p3 = ex2f(s3);
        smA += p0; smB += p1; smC += p2; smD += p3;
        ull pA = pk2(p0, p0), pB = pk2(p1, p1), pC = pk2(p2, p2), pD = pk2(p3, p3);
        const ulonglong2* vr = (const ulonglong2*)(vsm + m*VS_STRIDE);
        ulonglong2 vA = vr[0], vB = vr[1];
        aA[0] = ffma2(pA, vA.x, aA[0]); aA[1] = ffma2(pA, vA.y, aA[1]);
        aA[2] = ffma2(pA, vB.x, aA[2]); aA[3] = ffma2(pA, vB.y, aA[3]);
        aB[0] = ffma2(pB, vA.x, aB[0]); aB[1] = ffma2(pB, vA.y, aB[1]);
        aB[2] = ffma2(pB, vB.x, aB[2]); aB[3] = ffma2(pB, vB.y, aB[3]);
        aC[0] = ffma2(pC, vA.x, aC[0]); aC[1] = ffma2(pC, vA.y, aC[1]);
        aC[2] = ffma2(pC, vB.x, aC[2]); aC[3] = ffma2(pC, vB.y, aC[3]);
        aD[0] = ffma2(pD, vA.x, aD[0]); aD[1] = ffma2(pD, vA.y, aD[1]);
        aD[2] = ffma2(pD, vB.x, aD[2]); aD[3] = ffma2(pD, vB.y, aD[3]);
    }

    // write partial sums (no division yet)
    float* pn = g_pn + (size_t)sp*N1;
    float* pd = g_pd + (size_t)sp*D1;
    size_t di = (size_t)bh*LL + lb;
    pd[di      ] = smA;
    pd[di + 256] = smB;
    pd[di + 512] = smC;
    pd[di + 768] = smD;
    #pragma unroll
    for (int j = 0; j < 4; j++) {
        float x0, x1, y0, y1, z0, z1, w0, w1;
        upk2(aA[j], x0, x1); upk2(aB[j], y0, y1);
        upk2(aC[j], z0, z1); upk2(aD[j], w0, w1);
        size_t r0 = qb + (size_t)(2*j)*LL;
        size_t r1 = r0 + LL;
        pn[r0      ] = x0; pn[r1      ] = x1;
        pn[r0 + 256] = y0; pn[r1 + 256] = y1;
        pn[r0 + 512] = z0; pn[r1 + 512] = z1;
        pn[r0 + 768] = w0; pn[r1 + 768] = w1;
    }
}

// ---------------- K5: combine + out conv + residual + stats (k4b fused in) ----------------
#define TL5 128
__global__ void __launch_bounds__(256) k5_outconv(const float* __restrict__ ow) {
    __shared__ float xcs[48][TL5 + 2];
    int t = threadIdx.x;
    int l0 = blockIdx.x * TL5, g = blockIdx.y, b = blockIdx.z;
    const int W = TL5 + 2;
    for (int idx = t; idx < 48*W; idx += 256) {
        int j = idx / W, s = idx % W;
        int l = l0 - 1 + s;
        int u = g*48 + j;
        float val = 0.f;
        if (l >= 0 && l < LL) {
            if (u < 64) {
                size_t ii = ((size_t)b*CC + u)*LL + l;
                size_t di = ((size_t)(b*HH + (u >> 3)))*LL + l;
                val = comb_o(ii, di) + g_xat[ii];           // xs = out + x_atten
            } else if (u < 128) {
                val = g_qp[((size_t)b*CC + (u - 64))*LL + l];
            } else {
                int ch = u - 128;
                size_t ii = ((size_t)b*CC + ch)*LL + l;
                size_t di = ((size_t)(b*HH + (ch >> 3)))*LL + l;
                val = comb_o(ii, di);                       // out
            }
        }
        xcs[j][s] = val;
    }
    __syncthreads();
    int cl = t >> 4, sub = t & 15;
    int c = g*CPG + cl;
    int lbase = sub * 8;
    float acc[8];
    #pragma unroll
    for (int jj = 0; jj < 8; jj++) acc[jj] = 0.f;
    const float* wb = ow + (size_t)c*48*3;
    for (int j = 0; j < 48; j++) {
        float w0 = __ldg(wb + j*3 + 0), w1 = __ldg(wb + j*3 + 1), w2 = __ldg(wb + j*3 + 2);
        const float* row = xcs[j];
        float a0 = row[lbase], a1 = row[lbase+1];
        #pragma unroll
        for (int jj = 0; jj < 8; jj++) {
            float a2 = row[lbase + 2 + jj];
            acc[jj] = fmaf(w0, a0, fmaf(w1, a1, fmaf(w2, a2, acc[jj])));
            a0 = a1; a1 = a2;
        }
    }
    float s1 = 0.f, s2 = 0.f;
    size_t base = ((size_t)b*CC + c)*LL + l0 + lbase;
    size_t dbase = ((size_t)(b*HH + (c >> 3)))*LL + l0 + lbase;
    #pragma unroll
    for (int jj = 0; jj < 8; jj++) {
        size_t ii = base + jj;
        float xs = comb_o(ii, dbase + jj) + g_xat[ii];      // residual xs
        float v = acc[jj] + xs;
        g_xs2[ii] = v;
        s1 += v; s2 = fmaf(v, v, s2);
    }
    #pragma unroll
    for (int k = 1; k < 16; k <<= 1) {
        s1 += __shfl_xor_sync(0xffffffffu, s1, k);
        s2 += __shfl_xor_sync(0xffffffffu, s2, k);
    }
    if (sub == 0) { atomicAdd(&g_s1f[c], s1); atomicAdd(&g_s2f[c], s2); }
}

// ---------------- K6: final BN + ReLU -> output ----------------
__global__ void __launch_bounds__(256) k6_final(const float* __restrict__ gam,
                                                const float* __restrict__ bet,
                                                float* __restrict__ out) {
    int idx = blockIdx.x * 256 + threadIdx.x;
    int c = (idx >> 11) & (CC-1);
    const float invn = 1.f / (float)(BB*LL);
    float mean = g_s1f[c] * invn;
    float var  = g_s2f[c] * invn - mean*mean;
    float s  = gam[c] * rsqrtf(var + EPSV);
    float shv = bet[c] - mean*s;
    out[idx] = fmaxf(0.f, fmaf(g_xs2[idx], s, shv));
}

// ---------------- launch ----------------
extern "C" void kernel_launch(void* const* d_in, const int* in_sizes, int n_in,
                              void* d_out, int out_size) {
    const float* x   = (const float*)d_in[0];
    const float* qw  = (const float*)d_in[1];
    const float* kw  = (const float*)d_in[2];
    const float* vw  = (const float*)d_in[3];
    const float* v1w = (const float*)d_in[4];
    const float* ow  = (const float*)d_in[5];
    const float* dw  = (const float*)d_in[6];
    const float* dg  = (const float*)d_in[7];
    const float* db  = (const float*)d_in[8];
    const float* gam = (const float*)d_in[9];
    const float* bet = (const float*)d_in[10];
    float* out = (float*)d_out;

    k1_gate<<<dim3((BB*LL)/256, GG), 256>>>(x, qw, kw);
    k2_down<<<dim3(MM/TM2, BB), 256>>>(dw);
    k3_vconv<<<dim3((BB*MM)/256, GG), 256>>>(vw, v1w, dg, db);
    k4_attn<<<dim3(LL/1024, BB*HH, SPL), 256, K4_SMEM>>>();
    k5_outconv<<<dim3(LL/TL5, GG, BB), 256>>>(ow);
    k6_final<<<(BB*CC*LL)/256, 256>>>(gam, bet, out);
}

// round 8
// speedup vs baseline: 1.4928x; 1.4695x over previous
#include <cuda_runtime.h>
#include <math.h>
#include <stdint.h>

#define BB 8
#define CC 64
#define LL 2048
#define MM 1024
#define GG 4
#define CPG 16
#define HH 8
#define EE 8
#define EPSV 1e-5f

__device__ __forceinline__ float ex2f(float x) {
    float r;
    asm("ex2.approx.f32 %0, %1;" : "=f"(r) : "f"(x));
    return r;
}
__device__ __forceinline__ uint32_t tf32r(float x) {
    uint32_t u;
    asm("cvt.rna.tf32.f32 %0, %1;" : "=r"(u) : "f"(x));
    return u;
}
// D = A*B + C  (m16n8k8 tf32)
__device__ __forceinline__ void mma8(float& d0, float& d1, float& d2, float& d3,
                                     uint32_t a0, uint32_t a1, uint32_t a2, uint32_t a3,
                                     uint32_t b0, uint32_t b1,
                                     float c0, float c1, float c2, float c3) {
    asm volatile(
        "mma.sync.aligned.m16n8k8.row.col.f32.tf32.tf32.f32 "
        "{%0,%1,%2,%3},{%4,%5,%6,%7},{%8,%9},{%10,%11,%12,%13};"
        : "=f"(d0), "=f"(d1), "=f"(d2), "=f"(d3)
        : "r"(a0), "r"(a1), "r"(a2), "r"(a3), "r"(b0), "r"(b1),
          "f"(c0), "f"(c1), "f"(c2), "f"(c3));
}
// D += A*B
__device__ __forceinline__ void mma8acc(float& d0, float& d1, float& d2, float& d3,
                                        uint32_t a0, uint32_t a1, uint32_t a2, uint32_t a3,
                                        uint32_t b0, uint32_t b1) {
    asm volatile(
        "mma.sync.aligned.m16n8k8.row.col.f32.tf32.tf32.f32 "
        "{%0,%1,%2,%3},{%4,%5,%6,%7},{%8,%9},{%0,%1,%2,%3};"
        : "+f"(d0), "+f"(d1), "+f"(d2), "+f"(d3)
        : "r"(a0), "r"(a1), "r"(a2), "r"(a3), "r"(b0), "r"(b1));
}

// ---------------- scratch ----------------
__device__ float g_xat[BB*CC*LL];
__device__ float g_qp [BB*CC*LL];
__device__ float g_xa [BB*CC*MM];
__device__ float g_v  [BB*CC*MM];
__device__ float g_v1 [BB*CC*MM];
__device__ float g_out[BB*CC*LL];
__device__ float g_xs [BB*CC*LL];
__device__ float g_xs2[BB*CC*LL];
__device__ float g_s1d[CC];
__device__ float g_s2d[CC];
__device__ float g_s1f[CC];
__device__ float g_s2f[CC];

// ---------------- K1: q conv -> sigmoid gate -> x_atten -> q_ conv ----------------
__global__ void __launch_bounds__(256) k1_gate(const float* __restrict__ x,
                                               const float* __restrict__ qw,
                                               const float* __restrict__ kw) {
    __shared__ float qws[CPG*CPG], kws[CPG*CPG];
    int t = threadIdx.x;
    int g = blockIdx.y;
    if (blockIdx.x == 0 && g == 0 && t < CC) {
        g_s1d[t] = 0.f; g_s2d[t] = 0.f; g_s1f[t] = 0.f; g_s2f[t] = 0.f;
    }
    if (t < CPG*CPG) {
        qws[t] = qw[(size_t)g*CPG*CPG + t];
        kws[t] = kw[(size_t)g*CPG*CPG + t];
    }
    __syncthreads();
    int gl = blockIdx.x * 256 + t;
    int b = gl >> 11, l = gl & (LL-1);
    size_t base = (size_t)b*CC*LL + l + (size_t)g*CPG*LL;
    float xv[CPG], xa[CPG];
    #pragma unroll
    for (int i = 0; i < CPG; i++) xv[i] = x[base + (size_t)i*LL];
    #pragma unroll
    for (int c = 0; c < CPG; c++) {
        float s = 0.f;
        #pragma unroll
        for (int i = 0; i < CPG; i++) s = fmaf(qws[c*CPG+i], xv[i], s);
        xa[c] = xv[c] / (1.f + __expf(-s));
    }
    #pragma unroll
    for (int i = 0; i < CPG; i++) g_xat[base + (size_t)i*LL] = xa[i];
    #pragma unroll
    for (int c = 0; c < CPG; c++) {
        float s = 0.f;
        #pragma unroll
        for (int i = 0; i < CPG; i++) s = fmaf(kws[c*CPG+i], xa[i], s);
        g_qp[base + (size_t)c*LL] = s;
    }
}

// ---------------- K2: odd/even shuffle + down conv + BN stats ----------------
#define TM2 32
__global__ void __launch_bounds__(256) k2_down(const float* __restrict__ dw) {
    __shared__ float xt[CC][2*TM2 + 4];
    int t = threadIdx.x;
    int m0 = blockIdx.x * TM2, b = blockIdx.y;
    int l0 = 2*m0 - 2;
    const int W = 2*TM2 + 4;
    for (int idx = t; idx < CC*W; idx += 256) {
        int i = idx / W, s = idx % W;
        int l = l0 + s;
        xt[i][s] = (l >= 0 && l < LL) ? g_xat[((size_t)b*CC + i)*LL + l] : 0.f;
    }
    __syncthreads();
    int o = t >> 2, qq = t & 3;
    float acc[8];
    #pragma unroll
    for (int j = 0; j < 8; j++) acc[j] = 0.f;
    const float* wb = dw + (size_t)o*CC*3;
    int sb = 2*(qq*8) + ((o < 32) ? 1 : 0);
    for (int i = 0; i < CC; i++) {
        float w0 = __ldg(wb + i*3 + 0), w1 = __ldg(wb + i*3 + 1), w2 = __ldg(wb + i*3 + 2);
        const float* row = xt[i];
        float a0 = row[sb], a1 = row[sb+2];
        #pragma unroll
        for (int j = 0; j < 8; j++) {
            float a2 = row[sb + 4 + 2*j];
            acc[j] = fmaf(w0, a0, fmaf(w1, a1, fmaf(w2, a2, acc[j])));
            a0 = a1; a1 = a2;
        }
    }
    float s1 = 0.f, s2 = 0.f;
    size_t base = ((size_t)b*CC + o)*MM + m0 + qq*8;
    #pragma unroll
    for (int j = 0; j < 8; j++) { float v = acc[j]; g_xa[base + j] = v; s1 += v; s2 = fmaf(v, v, s2); }
    s1 += __shfl_xor_sync(0xffffffffu, s1, 1); s2 += __shfl_xor_sync(0xffffffffu, s2, 1);
    s1 += __shfl_xor_sync(0xffffffffu, s1, 2); s2 += __shfl_xor_sync(0xffffffffu, s2, 2);
    if (qq == 0) { atomicAdd(&g_s1d[o], s1); atomicAdd(&g_s2d[o], s2); }
}

// ---------------- K3: BN + ReLU + v/v1 pointwise grouped convs ----------------
__global__ void __launch_bounds__(256) k3_vconv(const float* __restrict__ vw,
                                                const float* __restrict__ v1w,
                                                const float* __restrict__ dgam,
                                                const float* __restrict__ dbet) {
    __shared__ float sc[CPG], sh[CPG], vws[CPG*CPG], v1ws[CPG*CPG];
    int t = threadIdx.x;
    int g = blockIdx.y;
    if (t < CPG) {
        int c = g*CPG + t;
        const float invn = 1.f / (float)(BB*MM);
        float mean = g_s1d[c] * invn;
        float var  = g_s2d[c] * invn - mean*mean;
        float s = dgam[c] * rsqrtf(var + EPSV);
        sc[t] = s; sh[t] = dbet[c] - mean*s;
    }
    if (t < CPG*CPG) {
        vws[t]  = vw [(size_t)g*CPG*CPG + t];
        v1ws[t] = v1w[(size_t)g*CPG*CPG + t];
    }
    __syncthreads();
    int gl = blockIdx.x * 256 + t;
    int b = gl >> 10, m = gl & (MM-1);
    size_t base = (size_t)b*CC*MM + m + (size_t)g*CPG*MM;
    float xr[CPG];
    #pragma unroll
    for (int i = 0; i < CPG; i++)
        xr[i] = fmaxf(0.f, fmaf(g_xa[base + (size_t)i*MM], sc[i], sh[i]));
    #pragma unroll
    for (int c = 0; c < CPG; c++) {
        float s = 0.f, s1 = 0.f;
        #pragma unroll
        for (int i = 0; i < CPG; i++) {
            s  = fmaf(vws [c*CPG+i], xr[i], s);
            s1 = fmaf(v1ws[c*CPG+i], xr[i], s1);
        }
        g_v [base + (size_t)c*MM] = s;
        g_v1[base + (size_t)c*MM] = s1;
    }
}

// ---------------- K4: mma.sync tf32 flash attention ----------------
// Block: (l-tile of 128) x (bh). 8 warps, each warp 16 l-rows, full M=1024 loop.
// Smem: KB/VB pre-permuted B-fragments: KB[chunk][lane] = {K[2j][m0+g], K[2j+1][m0+g]}
//       VB[chunk][lane] = {V[m0+2j][g], V[m0+2j+1][g]}   (j=lane%4, g=lane/4)
#define K4M_SMEM (2*128*32*8)   // 65536 bytes

__global__ void __launch_bounds__(256) k4_mma() {
    extern __shared__ float2 sm4[];
    float2* KB = sm4;            // [4096]
    float2* VB = sm4 + 4096;     // [4096]
    int t = threadIdx.x;
    int bh = blockIdx.y;
    size_t vb = (size_t)bh * EE * MM;     // b*CC + h*8 == 8*bh
    const float SCL = 0.35355339059327373f * 1.4426950408889634f;  // 1/sqrt(E)*log2(e)

    for (int i = t; i < 4096; i += 256) {
        int lane = i & 31, chunk = i >> 5;
        int j = lane & 3, g = lane >> 2;
        int m = chunk*8 + g;
        float k0 = g_v[vb + (size_t)(2*j  )*MM + m] * SCL;
        float k1 = g_v[vb + (size_t)(2*j+1)*MM + m] * SCL;
        float2 kk; kk.x = __uint_as_float(tf32r(k0)); kk.y = __uint_as_float(tf32r(k1));
        KB[i] = kk;
        float2 vv = *(const float2*)(g_v1 + vb + (size_t)g*MM + chunk*8 + 2*j);
        float2 vt; vt.x = __uint_as_float(tf32r(vv.x)); vt.y = __uint_as_float(tf32r(vv.y));
        VB[i] = vt;
    }
    __syncthreads();

    int lane = t & 31, wid = t >> 5;
    int j = lane & 3, g = lane >> 2;
    int lr = blockIdx.x*128 + wid*16 + g;
    size_t qbase = (size_t)(8*bh)*LL;

    // Q fragment (A of GEMM1): a0=[g][2j] a1=[g][2j+1] a2=[g+8][2j] a3=[g+8][2j+1]
    uint32_t qa0 = tf32r(g_qp[qbase + (size_t)(2*j  )*LL + lr    ]);
    uint32_t qa1 = tf32r(g_qp[qbase + (size_t)(2*j+1)*LL + lr    ]);
    uint32_t qa2 = tf32r(g_qp[qbase + (size_t)(2*j  )*LL + lr + 8]);
    uint32_t qa3 = tf32r(g_qp[qbase + (size_t)(2*j+1)*LL + lr + 8]);

    float d0 = 0.f, d1 = 0.f, d2 = 0.f, d3 = 0.f;
    float den0 = 0.f, den1 = 0.f;
    const float2* kb = KB + lane;
    const float2* vp = VB + lane;
    const float zf = 0.f;

    #pragma unroll 2
    for (int c = 0; c < 128; c++) {
        float2 kk = kb[c*32];
        float2 vv = vp[c*32];
        float s0, s1, s2, s3;
        mma8(s0, s1, s2, s3, qa0, qa1, qa2, qa3,
             __float_as_uint(kk.x), __float_as_uint(kk.y), zf, zf, zf, zf);
        // exp (base-2, scale folded into K) + tf32 round; den sums the ROUNDED p
        uint32_t p0 = tf32r(ex2f(s0));
        uint32_t p1 = tf32r(ex2f(s1));
        uint32_t p2 = tf32r(ex2f(s2));
        uint32_t p3 = tf32r(ex2f(s3));
        den0 += __uint_as_float(p0) + __uint_as_float(p1);
        den1 += __uint_as_float(p2) + __uint_as_float(p3);
        mma8acc(d0, d1, d2, d3, p0, p1, p2, p3,
                __float_as_uint(vv.x), __float_as_uint(vv.y));
    }

    // reduce denominators across the 4-thread quad (they cover n = 0..7)
    den0 += __shfl_xor_sync(0xffffffffu, den0, 1);
    den0 += __shfl_xor_sync(0xffffffffu, den0, 2);
    den1 += __shfl_xor_sync(0xffffffffu, den1, 1);
    den1 += __shfl_xor_sync(0xffffffffu, den1, 2);
    float i0 = 1.f / den0, i1 = 1.f / den1;

    // D fragment: d0=[lr][2j] d1=[lr][2j+1] d2=[lr+8][2j] d3=[lr+8][2j+1]
    size_t iA = qbase + (size_t)(2*j)*LL + lr;       // e=2j,   row lr
    size_t iB = iA + LL;                             // e=2j+1, row lr
    float o;
    o = d0*i0; g_out[iA    ] = o; g_xs[iA    ] = o + g_xat[iA    ];
    o = d1*i0; g_out[iB    ] = o; g_xs[iB    ] = o + g_xat[iB    ];
    o = d2*i1; g_out[iA + 8] = o; g_xs[iA + 8] = o + g_xat[iA + 8];
    o = d3*i1; g_out[iB + 8] = o; g_xs[iB + 8] = o + g_xat[iB + 8];
}

// ---------------- K5: out conv (K=3, groups=4 over concat(xs,q_,out)) + residual + stats ----------------
#define TL5 128
__global__ void __launch_bounds__(256) k5_outconv(const float* __restrict__ ow) {
    __shared__ float xcs[48][TL5 + 2];
    int t = threadIdx.x;
    int l0 = blockIdx.x * TL5, g = blockIdx.y, b = blockIdx.z;
    const int W = TL5 + 2;
    for (int idx = t; idx < 48*W; idx += 256) {
        int j = idx / W, s = idx % W;
        int l = l0 - 1 + s;
        int u = g*48 + j;
        float val = 0.f;
        if (l >= 0 && l < LL) {
            const float* src; int ch;
            if      (u < 64)  { src = g_xs;  ch = u; }
            else if (u < 128) { src = g_qp;  ch = u - 64; }
            else              { src = g_out; ch = u - 128; }
            val = src[((size_t)b*CC + ch)*LL + l];
        }
        xcs[j][s] = val;
    }
    __syncthreads();
    int cl = t >> 4, sub = t & 15;
    int c = g*CPG + cl;
    int lbase = sub * 8;
    float acc[8];
    #pragma unroll
    for (int jj = 0; jj < 8; jj++) acc[jj] = 0.f;
    const float* wb = ow + (size_t)c*48*3;
    for (int j = 0; j < 48; j++) {
        float w0 = __ldg(wb + j*3 + 0), w1 = __ldg(wb + j*3 + 1), w2 = __ldg(wb + j*3 + 2);
        const float* row = xcs[j];
        float a0 = row[lbase], a1 = row[lbase+1];
        #pragma unroll
        for (int jj = 0; jj < 8; jj++) {
            float a2 = row[lbase + 2 + jj];
            acc[jj] = fmaf(w0, a0, fmaf(w1, a1, fmaf(w2, a2, acc[jj])));
            a0 = a1; a1 = a2;
        }
    }
    float s1 = 0.f, s2 = 0.f;
    size_t base = ((size_t)b*CC + c)*LL + l0 + lbase;
    #pragma unroll
    for (int jj = 0; jj < 8; jj++) {
        float v = acc[jj] + g_xs[base + jj];
        g_xs2[base + jj] = v;
        s1 += v; s2 = fmaf(v, v, s2);
    }
    #pragma unroll
    for (int k = 1; k < 16; k <<= 1) {
        s1 += __shfl_xor_sync(0xffffffffu, s1, k);
        s2 += __shfl_xor_sync(0xffffffffu, s2, k);
    }
    if (sub == 0) { atomicAdd(&g_s1f[c], s1); atomicAdd(&g_s2f[c], s2); }
}

// ---------------- K6: final BN + ReLU -> output ----------------
__global__ void __launch_bounds__(256) k6_final(const float* __restrict__ gam,
                                                const float* __restrict__ bet,
                                                float* __restrict__ out) {
    int idx = blockIdx.x * 256 + threadIdx.x;
    int c = (idx >> 11) & (CC-1);
    const float invn = 1.f / (float)(BB*LL);
    float mean = g_s1f[c] * invn;
    float var  = g_s2f[c] * invn - mean*mean;
    float s  = gam[c] * rsqrtf(var + EPSV);
    float shv = bet[c] - mean*s;
    out[idx] = fmaxf(0.f, fmaf(g_xs2[idx], s, shv));
}

// ---------------- launch ----------------
extern "C" void kernel_launch(void* const* d_in, const int* in_sizes, int n_in,
                              void* d_out, int out_size) {
    const float* x   = (const float*)d_in[0];
    const float* qw  = (const float*)d_in[1];
    const float* kw  = (const float*)d_in[2];
    const float* vw  = (const float*)d_in[3];
    const float* v1w = (const float*)d_in[4];
    const float* ow  = (const float*)d_in[5];
    const float* dw  = (const float*)d_in[6];
    const float* dg  = (const float*)d_in[7];
    const float* db  = (const float*)d_in[8];
    const float* gam = (const float*)d_in[9];
    const float* bet = (const float*)d_in[10];
    float* out = (float*)d_out;

    static int configured = 0;
    if (!configured) {
        cudaFuncSetAttribute(k4_mma, cudaFuncAttributeMaxDynamicSharedMemorySize, K4M_SMEM);
        configured = 1;
    }

    k1_gate<<<dim3((BB*LL)/256, GG), 256>>>(x, qw, kw);
    k2_down<<<dim3(MM/TM2, BB), 256>>>(dw);
    k3_vconv<<<dim3((BB*MM)/256, GG), 256>>>(vw, v1w, dg, db);
    k4_mma<<<dim3(LL/128, BB*HH), 256, K4M_SMEM>>>();
    k5_outconv<<<dim3(LL/TL5, GG, BB), 256>>>(ow);
    k6_final<<<(BB*CC*LL)/256, 256>>>(gam, bet, out);
}

// round 9
// speedup vs baseline: 1.5537x; 1.0408x over previous
#include <cuda_runtime.h>
#include <math.h>
#include <stdint.h>

#define BB 8
#define CC 64
#define LL 2048
#define MM 1024
#define GG 4
#define CPG 16
#define HH 8
#define EE 8
#define EPSV 1e-5f

__device__ __forceinline__ float ex2f(float x) {
    float r;
    asm("ex2.approx.f32 %0, %1;" : "=f"(r) : "f"(x));
    return r;
}
__device__ __forceinline__ uint32_t tf32r(float x) {
    uint32_t u;
    asm("cvt.rna.tf32.f32 %0, %1;" : "=r"(u) : "f"(x));
    return u;
}
// D = A*B + C  (m16n8k8 tf32)
__device__ __forceinline__ void mma8(float& d0, float& d1, float& d2, float& d3,
                                     uint32_t a0, uint32_t a1, uint32_t a2, uint32_t a3,
                                     uint32_t b0, uint32_t b1,
                                     float c0, float c1, float c2, float c3) {
    asm volatile(
        "mma.sync.aligned.m16n8k8.row.col.f32.tf32.tf32.f32 "
        "{%0,%1,%2,%3},{%4,%5,%6,%7},{%8,%9},{%10,%11,%12,%13};"
        : "=f"(d0), "=f"(d1), "=f"(d2), "=f"(d3)
        : "r"(a0), "r"(a1), "r"(a2), "r"(a3), "r"(b0), "r"(b1),
          "f"(c0), "f"(c1), "f"(c2), "f"(c3));
}
// D += A*B
__device__ __forceinline__ void mma8acc(float& d0, float& d1, float& d2, float& d3,
                                        uint32_t a0, uint32_t a1, uint32_t a2, uint32_t a3,
                                        uint32_t b0, uint32_t b1) {
    asm volatile(
        "mma.sync.aligned.m16n8k8.row.col.f32.tf32.tf32.f32 "
        "{%0,%1,%2,%3},{%4,%5,%6,%7},{%8,%9},{%0,%1,%2,%3};"
        : "+f"(d0), "+f"(d1), "+f"(d2), "+f"(d3)
        : "r"(a0), "r"(a1), "r"(a2), "r"(a3), "r"(b0), "r"(b1));
}

// ---------------- scratch ----------------
__device__ float g_xat[BB*CC*LL];
__device__ float g_qp [BB*CC*LL];
__device__ float g_xa [BB*CC*MM];
__device__ float g_v  [BB*CC*MM];
__device__ float g_v1 [BB*CC*MM];
__device__ float g_out[BB*CC*LL];
__device__ float g_xs [BB*CC*LL];
__device__ float g_xs2[BB*CC*LL];
__device__ float g_s1d[CC];
__device__ float g_s2d[CC];
__device__ float g_s1f[CC];
__device__ float g_s2f[CC];

// ---------------- K1: q conv -> sigmoid gate -> x_atten -> q_ conv ----------------
__global__ void __launch_bounds__(256) k1_gate(const float* __restrict__ x,
                                               const float* __restrict__ qw,
                                               const float* __restrict__ kw) {
    __shared__ float qws[CPG*CPG], kws[CPG*CPG];
    int t = threadIdx.x;
    int g = blockIdx.y;
    if (blockIdx.x == 0 && g == 0 && t < CC) {
        g_s1d[t] = 0.f; g_s2d[t] = 0.f; g_s1f[t] = 0.f; g_s2f[t] = 0.f;
    }
    if (t < CPG*CPG) {
        qws[t] = qw[(size_t)g*CPG*CPG + t];
        kws[t] = kw[(size_t)g*CPG*CPG + t];
    }
    __syncthreads();
    int gl = blockIdx.x * 256 + t;
    int b = gl >> 11, l = gl & (LL-1);
    size_t base = (size_t)b*CC*LL + l + (size_t)g*CPG*LL;
    float xv[CPG], xa[CPG];
    #pragma unroll
    for (int i = 0; i < CPG; i++) xv[i] = x[base + (size_t)i*LL];
    #pragma unroll
    for (int c = 0; c < CPG; c++) {
        float s = 0.f;
        #pragma unroll
        for (int i = 0; i < CPG; i++) s = fmaf(qws[c*CPG+i], xv[i], s);
        xa[c] = xv[c] / (1.f + __expf(-s));
    }
    #pragma unroll
    for (int i = 0; i < CPG; i++) g_xat[base + (size_t)i*LL] = xa[i];
    #pragma unroll
    for (int c = 0; c < CPG; c++) {
        float s = 0.f;
        #pragma unroll
        for (int i = 0; i < CPG; i++) s = fmaf(kws[c*CPG+i], xa[i], s);
        g_qp[base + (size_t)c*LL] = s;
    }
}

// ---------------- K2: odd/even shuffle + down conv + BN stats ----------------
#define TM2 32
__global__ void __launch_bounds__(256) k2_down(const float* __restrict__ dw) {
    __shared__ float xt[CC][2*TM2 + 4];
    int t = threadIdx.x;
    int m0 = blockIdx.x * TM2, b = blockIdx.y;
    int l0 = 2*m0 - 2;
    const int W = 2*TM2 + 4;
    for (int idx = t; idx < CC*W; idx += 256) {
        int i = idx / W, s = idx % W;
        int l = l0 + s;
        xt[i][s] = (l >= 0 && l < LL) ? g_xat[((size_t)b*CC + i)*LL + l] : 0.f;
    }
    __syncthreads();
    int o = t >> 2, qq = t & 3;
    float acc[8];
    #pragma unroll
    for (int j = 0; j < 8; j++) acc[j] = 0.f;
    const float* wb = dw + (size_t)o*CC*3;
    int sb = 2*(qq*8) + ((o < 32) ? 1 : 0);
    for (int i = 0; i < CC; i++) {
        float w0 = __ldg(wb + i*3 + 0), w1 = __ldg(wb + i*3 + 1), w2 = __ldg(wb + i*3 + 2);
        const float* row = xt[i];
        float a0 = row[sb], a1 = row[sb+2];
        #pragma unroll
        for (int j = 0; j < 8; j++) {
            float a2 = row[sb + 4 + 2*j];
            acc[j] = fmaf(w0, a0, fmaf(w1, a1, fmaf(w2, a2, acc[j])));
            a0 = a1; a1 = a2;
        }
    }
    float s1 = 0.f, s2 = 0.f;
    size_t base = ((size_t)b*CC + o)*MM + m0 + qq*8;
    #pragma unroll
    for (int j = 0; j < 8; j++) { float v = acc[j]; g_xa[base + j] = v; s1 += v; s2 = fmaf(v, v, s2); }
    s1 += __shfl_xor_sync(0xffffffffu, s1, 1); s2 += __shfl_xor_sync(0xffffffffu, s2, 1);
    s1 += __shfl_xor_sync(0xffffffffu, s1, 2); s2 += __shfl_xor_sync(0xffffffffu, s2, 2);
    if (qq == 0) { atomicAdd(&g_s1d[o], s1); atomicAdd(&g_s2d[o], s2); }
}

// ---------------- K3: BN + ReLU + v/v1 pointwise grouped convs ----------------
__global__ void __launch_bounds__(256) k3_vconv(const float* __restrict__ vw,
                                                const float* __restrict__ v1w,
                                                const float* __restrict__ dgam,
                                                const float* __restrict__ dbet) {
    __shared__ float sc[CPG], sh[CPG], vws[CPG*CPG], v1ws[CPG*CPG];
    int t = threadIdx.x;
    int g = blockIdx.y;
    if (t < CPG) {
        int c = g*CPG + t;
        const float invn = 1.f / (float)(BB*MM);
        float mean = g_s1d[c] * invn;
        float var  = g_s2d[c] * invn - mean*mean;
        float s = dgam[c] * rsqrtf(var + EPSV);
        sc[t] = s; sh[t] = dbet[c] - mean*s;
    }
    if (t < CPG*CPG) {
        vws[t]  = vw [(size_t)g*CPG*CPG + t];
        v1ws[t] = v1w[(size_t)g*CPG*CPG + t];
    }
    __syncthreads();
    int gl = blockIdx.x * 256 + t;
    int b = gl >> 10, m = gl & (MM-1);
    size_t base = (size_t)b*CC*MM + m + (size_t)g*CPG*MM;
    float xr[CPG];
    #pragma unroll
    for (int i = 0; i < CPG; i++)
        xr[i] = fmaxf(0.f, fmaf(g_xa[base + (size_t)i*MM], sc[i], sh[i]));
    #pragma unroll
    for (int c = 0; c < CPG; c++) {
        float s = 0.f, s1 = 0.f;
        #pragma unroll
        for (int i = 0; i < CPG; i++) {
            s  = fmaf(vws [c*CPG+i], xr[i], s);
            s1 = fmaf(v1ws[c*CPG+i], xr[i], s1);
        }
        g_v [base + (size_t)c*MM] = s;
        g_v1[base + (size_t)c*MM] = s1;
    }
}

// ---------------- K4: mma.sync tf32 flash attention, (p-1) decomposition ----------------
// out_e = (colsum_e + sum_m (p_m - 1) v_em) / (1024 + sum_m (p_m - 1))
// The "1" part of each softmax weight multiplies an exact fp32 column sum, so
// tf32 rounding only touches the small residual (p-1) ~ 0.05.
// Smem: KB/VB pre-permuted B-fragments: KB[chunk][lane] = {K[2j][m0+g], K[2j+1][m0+g]}
//       VB[chunk][lane] = {V[m0+2j][g], V[m0+2j+1][g]}   (j=lane%4, g=lane/4)
#define K4M_SMEM (2*128*32*8 + 64)   // 65536 + colsum

__global__ void __launch_bounds__(256) k4_mma() {
    extern __shared__ float2 sm4[];
    float2* KB = sm4;            // [4096]
    float2* VB = sm4 + 4096;     // [4096]
    float* scv = (float*)(sm4 + 8192);   // [8] V column sums
    int t = threadIdx.x;
    int bh = blockIdx.y;
    size_t vb = (size_t)bh * EE * MM;     // b*CC + h*8 == 8*bh
    const float SCL = 0.35355339059327373f * 1.4426950408889634f;  // 1/sqrt(E)*log2(e)

    for (int i = t; i < 4096; i += 256) {
        int lane = i & 31, chunk = i >> 5;
        int j = lane & 3, g = lane >> 2;
        int m = chunk*8 + g;
        float k0 = g_v[vb + (size_t)(2*j  )*MM + m] * SCL;
        float k1 = g_v[vb + (size_t)(2*j+1)*MM + m] * SCL;
        float2 kk; kk.x = __uint_as_float(tf32r(k0)); kk.y = __uint_as_float(tf32r(k1));
        KB[i] = kk;
        float2 vv = *(const float2*)(g_v1 + vb + (size_t)g*MM + chunk*8 + 2*j);
        float2 vt; vt.x = __uint_as_float(tf32r(vv.x)); vt.y = __uint_as_float(tf32r(vv.y));
        VB[i] = vt;
    }
    // V column sums (exact fp32, from gmem): warp e sums row e
    {
        int lane = t & 31, wid = t >> 5;
        float s = 0.f;
        const float* vr = g_v1 + vb + (size_t)wid*MM;
        for (int m = lane; m < MM; m += 32) s += vr[m];
        #pragma unroll
        for (int o = 16; o; o >>= 1) s += __shfl_xor_sync(0xffffffffu, s, o);
        if (lane == 0) scv[wid] = s;
    }
    __syncthreads();

    int lane = t & 31, wid = t >> 5;
    int j = lane & 3, g = lane >> 2;
    int lr = blockIdx.x*128 + wid*16 + g;
    size_t qbase = (size_t)(8*bh)*LL;

    // Q fragment (A of GEMM1): a0=[g][2j] a1=[g][2j+1] a2=[g+8][2j] a3=[g+8][2j+1]
    uint32_t qa0 = tf32r(g_qp[qbase + (size_t)(2*j  )*LL + lr    ]);
    uint32_t qa1 = tf32r(g_qp[qbase + (size_t)(2*j+1)*LL + lr    ]);
    uint32_t qa2 = tf32r(g_qp[qbase + (size_t)(2*j  )*LL + lr + 8]);
    uint32_t qa3 = tf32r(g_qp[qbase + (size_t)(2*j+1)*LL + lr + 8]);

    float d0 = 0.f, d1 = 0.f, d2 = 0.f, d3 = 0.f;
    float den0 = 0.f, den1 = 0.f;
    const float2* kb = KB + lane;
    const float2* vp = VB + lane;
    const float zf = 0.f;

    #pragma unroll 2
    for (int c = 0; c < 128; c++) {
        float2 kk = kb[c*32];
        float2 vv = vp[c*32];
        float s0, s1, s2, s3;
        mma8(s0, s1, s2, s3, qa0, qa1, qa2, qa3,
             __float_as_uint(kk.x), __float_as_uint(kk.y), zf, zf, zf, zf);
        // p-1 in fp32 (raw bits fed to MMA: tf32 truncation of the small residual)
        float p0 = ex2f(s0) - 1.f;
        float p1 = ex2f(s1) - 1.f;
        float p2 = ex2f(s2) - 1.f;
        float p3 = ex2f(s3) - 1.f;
        den0 += p0 + p1;
        den1 += p2 + p3;
        mma8acc(d0, d1, d2, d3,
                __float_as_uint(p0), __float_as_uint(p1),
                __float_as_uint(p2), __float_as_uint(p3),
                __float_as_uint(vv.x), __float_as_uint(vv.y));
    }

    // reduce denominators across the 4-thread quad (they cover n = 0..7)
    den0 += __shfl_xor_sync(0xffffffffu, den0, 1);
    den0 += __shfl_xor_sync(0xffffffffu, den0, 2);
    den1 += __shfl_xor_sync(0xffffffffu, den1, 1);
    den1 += __shfl_xor_sync(0xffffffffu, den1, 2);
    float i0 = 1.f / ((float)MM + den0);
    float i1 = 1.f / ((float)MM + den1);

    // D fragment: d0=[lr][2j] d1=[lr][2j+1] d2=[lr+8][2j] d3=[lr+8][2j+1]
    float cs0 = scv[2*j], cs1 = scv[2*j+1];
    size_t iA = qbase + (size_t)(2*j)*LL + lr;       // e=2j,   row lr
    size_t iB = iA + LL;                             // e=2j+1, row lr
    float o;
    o = (cs0 + d0)*i0; g_out[iA    ] = o; g_xs[iA    ] = o + g_xat[iA    ];
    o = (cs1 + d1)*i0; g_out[iB    ] = o; g_xs[iB    ] = o + g_xat[iB    ];
    o = (cs0 + d2)*i1; g_out[iA + 8] = o; g_xs[iA + 8] = o + g_xat[iA + 8];
    o = (cs1 + d3)*i1; g_out[iB + 8] = o; g_xs[iB + 8] = o + g_xat[iB + 8];
}

// ---------------- K5: out conv (K=3, groups=4 over concat(xs,q_,out)) + residual + stats ----------------
#define TL5 128
__global__ void __launch_bounds__(256) k5_outconv(const float* __restrict__ ow) {
    __shared__ float xcs[48][TL5 + 2];
    int t = threadIdx.x;
    int l0 = blockIdx.x * TL5, g = blockIdx.y, b = blockIdx.z;
    const int W = TL5 + 2;
    for (int idx = t; idx < 48*W; idx += 256) {
        int j = idx / W, s = idx % W;
        int l = l0 - 1 + s;
        int u = g*48 + j;
        float val = 0.f;
        if (l >= 0 && l < LL) {
            const float* src; int ch;
            if      (u < 64)  { src = g_xs;  ch = u; }
            else if (u < 128) { src = g_qp;  ch = u - 64; }
            else              { src = g_out; ch = u - 128; }
            val = src[((size_t)b*CC + ch)*LL + l];
        }
        xcs[j][s] = val;
    }
    __syncthreads();
    int cl = t >> 4, sub = t & 15;
    int c = g*CPG + cl;
    int lbase = sub * 8;
    float acc[8];
    #pragma unroll
    for (int jj = 0; jj < 8; jj++) acc[jj] = 0.f;
    const float* wb = ow + (size_t)c*48*3;
    for (int j = 0; j < 48; j++) {
        float w0 = __ldg(wb + j*3 + 0), w1 = __ldg(wb + j*3 + 1), w2 = __ldg(wb + j*3 + 2);
        const float* row = xcs[j];
        float a0 = row[lbase], a1 = row[lbase+1];
        #pragma unroll
        for (int jj = 0; jj < 8; jj++) {
            float a2 = row[lbase + 2 + jj];
            acc[jj] = fmaf(w0, a0, fmaf(w1, a1, fmaf(w2, a2, acc[jj])));
            a0 = a1; a1 = a2;
        }
    }
    float s1 = 0.f, s2 = 0.f;
    size_t base = ((size_t)b*CC + c)*LL + l0 + lbase;
    #pragma unroll
    for (int jj = 0; jj < 8; jj++) {
        float v = acc[jj] + g_xs[base + jj];
        g_xs2[base + jj] = v;
        s1 += v; s2 = fmaf(v, v, s2);
    }
    #pragma unroll
    for (int k = 1; k < 16; k <<= 1) {
        s1 += __shfl_xor_sync(0xffffffffu, s1, k);
        s2 += __shfl_xor_sync(0xffffffffu, s2, k);
    }
    if (sub == 0) { atomicAdd(&g_s1f[c], s1); atomicAdd(&g_s2f[c], s2); }
}

// ---------------- K6: final BN + ReLU -> output ----------------
__global__ void __launch_bounds__(256) k6_final(const float* __restrict__ gam,
                                                const float* __restrict__ bet,
                                                float* __restrict__ out) {
    int idx = blockIdx.x * 256 + threadIdx.x;
    int c = (idx >> 11) & (CC-1);
    const float invn = 1.f / (float)(BB*LL);
    float mean = g_s1f[c] * invn;
    float var  = g_s2f[c] * invn - mean*mean;
    float s  = gam[c] * rsqrtf(var + EPSV);
    float shv = bet[c] - mean*s;
    out[idx] = fmaxf(0.f, fmaf(g_xs2[idx], s, shv));
}

// ---------------- launch ----------------
extern "C" void kernel_launch(void* const* d_in, const int* in_sizes, int n_in,
                              void* d_out, int out_size) {
    const float* x   = (const float*)d_in[0];
    const float* qw  = (const float*)d_in[1];
    const float* kw  = (const float*)d_in[2];
    const float* vw  = (const float*)d_in[3];
    const float* v1w = (const float*)d_in[4];
    const float* ow  = (const float*)d_in[5];
    const float* dw  = (const float*)d_in[6];
    const float* dg  = (const float*)d_in[7];
    const float* db  = (const float*)d_in[8];
    const float* gam = (const float*)d_in[9];
    const float* bet = (const float*)d_in[10];
    float* out = (float*)d_out;

    static int configured = 0;
    if (!configured) {
        cudaFuncSetAttribute(k4_mma, cudaFuncAttributeMaxDynamicSharedMemorySize, K4M_SMEM);
        configured = 1;
    }

    k1_gate<<<dim3((BB*LL)/256, GG), 256>>>(x, qw, kw);
    k2_down<<<dim3(MM/TM2, BB), 256>>>(dw);
    k3_vconv<<<dim3((BB*MM)/256, GG), 256>>>(vw, v1w, dg, db);
    k4_mma<<<dim3(LL/128, BB*HH), 256, K4M_SMEM>>>();
    k5_outconv<<<dim3(TL5 ? LL/TL5 : 1, GG, BB), 256>>>(ow);
    k6_final<<<(BB*CC*LL)/256, 256>>>(gam, bet, out);
}